// round 5
// baseline (speedup 1.0000x reference)
#include <cuda_runtime.h>
#include <cuda_bf16.h>
#include <cuda_fp16.h>
#include <math.h>
#include <stdint.h>

#define VSZ 8192

__device__ __align__(16) float g_enc[512 * 512];
__device__ __align__(16) float g_dec[128 * 512];
__device__ __align__(16) __half g_wvt[8192 * 512];   // [v][d] fp16

// ---------------- helpers ----------------
__device__ __forceinline__ uint32_t smem_u32(const void* p) {
    uint32_t a;
    asm("{ .reg .u64 t; cvta.to.shared.u64 t, %1; cvt.u32.u64 %0, t; }" : "=r"(a) : "l"(p));
    return a;
}
__device__ __forceinline__ void cpa16(uint32_t dst, const void* src) {
    asm volatile("cp.async.cg.shared.global [%0], [%1], 16;" :: "r"(dst), "l"(src));
}
#define CPA_COMMIT() asm volatile("cp.async.commit_group;" ::: "memory")
#define CPA_WAIT1()  asm volatile("cp.async.wait_group 1;" ::: "memory")
#define CPA_WAIT0()  asm volatile("cp.async.wait_group 0;" ::: "memory")

__device__ __forceinline__ void ldsm4(uint32_t* r, uint32_t a) {
    asm volatile("ldmatrix.sync.aligned.m8n8.x4.shared.b16 {%0,%1,%2,%3}, [%4];"
        : "=r"(r[0]), "=r"(r[1]), "=r"(r[2]), "=r"(r[3]) : "r"(a));
}
// fp16 inputs, fp16 accumulators (2 packed b32 regs)
__device__ __forceinline__ void mma_h(uint32_t* c, const uint32_t* a, const uint32_t* b) {
    asm("mma.sync.aligned.m16n8k16.row.col.f16.f16.f16.f16 "
        "{%0,%1}, {%2,%3,%4,%5}, {%6,%7}, {%0,%1};\n"
        : "+r"(c[0]), "+r"(c[1])
        : "r"(a[0]), "r"(a[1]), "r"(a[2]), "r"(a[3]), "r"(b[0]), "r"(b[1]));
}

// ---------------- prep kernels ----------------
// 4 rows per CTA: enc groups (bid<128), dec groups (bid>=128)
__global__ void k_encdec(const float* __restrict__ v, const float* __restrict__ t,
                         const float* __restrict__ W1, const float* __restrict__ b1,
                         const float* __restrict__ W2, const float* __restrict__ b2) {
    __shared__ float xr[4][512];
    int bid = blockIdx.x, tid = threadIdx.x;
    const float *in, *W, *bs; float* out;
    if (bid < 128) { in = v + (size_t)bid * 2048; W = W1; bs = b1; out = g_enc + (size_t)bid * 2048; }
    else { int r = bid - 128; in = t + (size_t)r * 2048; W = W2; bs = b2; out = g_dec + (size_t)r * 2048; }
    #pragma unroll
    for (int i = 0; i < 8; ++i) ((float*)xr)[i * 256 + tid] = in[i * 256 + tid];
    __syncthreads();
    int e = tid * 2;
    float b0 = bs[e], b1v = bs[e + 1];
    float a00 = b0, a01 = b1v, a10 = b0, a11 = b1v;
    float a20 = b0, a21 = b1v, a30 = b0, a31 = b1v;
    #pragma unroll 4
    for (int d = 0; d < 512; ++d) {
        float2 w = *(const float2*)&W[d * 512 + e];
        float x0 = xr[0][d], x1 = xr[1][d], x2 = xr[2][d], x3 = xr[3][d];
        a00 = fmaf(x0, w.x, a00); a01 = fmaf(x0, w.y, a01);
        a10 = fmaf(x1, w.x, a10); a11 = fmaf(x1, w.y, a11);
        a20 = fmaf(x2, w.x, a20); a21 = fmaf(x2, w.y, a21);
        a30 = fmaf(x3, w.x, a30); a31 = fmaf(x3, w.y, a31);
    }
    out[e] = a00;        out[e + 1] = a01;
    out[512 + e] = a10;  out[512 + e + 1] = a11;
    out[1024 + e] = a20; out[1024 + e + 1] = a21;
    out[1536 + e] = a30; out[1536 + e + 1] = a31;
}

__global__ void k_cvt(const float* __restrict__ Wv) {
    __shared__ float tile[32][33];
    int bvi = blockIdx.x & 255, bd = blockIdx.x >> 8;
    int v0 = bvi * 32, d0 = bd * 32;
    int c = threadIdx.x & 31, r8 = threadIdx.x >> 5;
    #pragma unroll
    for (int i = 0; i < 4; ++i) {
        int d = i * 8 + r8;
        tile[d][c] = Wv[(size_t)(d0 + d) * VSZ + v0 + c];
    }
    __syncthreads();
    #pragma unroll
    for (int i = 0; i < 4; ++i) {
        int vv = i * 8 + r8;
        g_wvt[(size_t)(v0 + vv) * 512 + d0 + c] = __float2half(tile[c][vv]);
    }
}

// ---------------- main GEMM + fused log-softmax ----------------
// CTA: 128 rows x full V. 8 warps, 2(M) x 4(N), warp tile 64x64, fp16 acc.
#define SA_STRB 1040                 // A row stride bytes (520 fp16)
#define SB_STRB 144                  // B row stride bytes (72 fp16)
#define A_BYTES (128 * SA_STRB)
#define B_BYTES (256 * SB_STRB)
#define DYN_SMEM (A_BYTES + 2 * B_BYTES)

__global__ void __launch_bounds__(256, 1)
k_gemm2(const float* __restrict__ bv, float* __restrict__ out) {
    extern __shared__ char sm[];
    __shared__ float pmax[4][128], psum[4][128];
    __shared__ float rmax[128], rsum[128], slse[128];

    const uint32_t sA = smem_u32(sm);
    const uint32_t sB0 = sA + A_BYTES;
    int tid = threadIdx.x, lane = tid & 31, w = tid >> 5;
    int wm = w >> 2, wn = w & 3;
    int q = lane >> 2, l4 = lane & 3;
    int r0 = blockIdx.x * 128;

    // ---- build A tile (relu(enc+dec) -> fp16) ----
    #pragma unroll 1
    for (int i = 0; i < 32; ++i) {
        int idx = i * 256 + tid;
        int r = idx >> 6, g = idx & 63;
        int grow = r0 + r;
        int er = grow >> 6;
        int dr = ((grow >> 14) << 6) | (grow & 63);
        const float* ep = g_enc + (size_t)er * 512 + g * 8;
        const float* dp = g_dec + (size_t)dr * 512 + g * 8;
        float4 e0 = *(const float4*)ep, e1 = *(const float4*)(ep + 4);
        float4 d0 = *(const float4*)dp, d1 = *(const float4*)(dp + 4);
        __half2 p0 = __floats2half2_rn(fmaxf(e0.x + d0.x, 0.f), fmaxf(e0.y + d0.y, 0.f));
        __half2 p1 = __floats2half2_rn(fmaxf(e0.z + d0.z, 0.f), fmaxf(e0.w + d0.w, 0.f));
        __half2 p2 = __floats2half2_rn(fmaxf(e1.x + d1.x, 0.f), fmaxf(e1.y + d1.y, 0.f));
        __half2 p3 = __floats2half2_rn(fmaxf(e1.z + d1.z, 0.f), fmaxf(e1.w + d1.w, 0.f));
        uint4 u;
        u.x = *(unsigned*)&p0; u.y = *(unsigned*)&p1; u.z = *(unsigned*)&p2; u.w = *(unsigned*)&p3;
        *(uint4*)(sm + r * SA_STRB + g * 16) = u;
    }
    if (tid < 128) { rmax[tid] = -1e30f; rsum[tid] = 0.f; }

    const uint32_t aBase = sA + (wm * 64 + (lane & 15)) * SA_STRB + (lane >> 4) * 16;
    const int bN = (lane & 7) + ((lane >> 4) << 3);
    const uint32_t bKh = ((lane >> 3) & 1) * 16;
    const uint32_t bBase = sB0 + (wn * 64 + bN) * SB_STRB + bKh;

    uint32_t acc[4][8][2];   // fp16x2 accumulators

    // stage slab 0
    {
        #pragma unroll
        for (int i = 0; i < 8; ++i) {
            int flat = i * 256 + tid;
            int n = flat >> 3, c = flat & 7;
            cpa16(sB0 + n * SB_STRB + c * 16, (const char*)g_wvt + (size_t)n * 1024 + c * 16);
        }
        CPA_COMMIT();
    }

    #pragma unroll 1
    for (int s = 0; s < 256; ++s) {
        int vc = s >> 3, kb = s & 7, buf = s & 1;
        __syncthreads();
        if (s + 1 < 256) {
            int vn = (s + 1) >> 3, kn = (s + 1) & 7;
            uint32_t dst = sB0 + ((s + 1) & 1) * B_BYTES;
            const char* src = (const char*)g_wvt + (size_t)vn * 256 * 1024 + kn * 128;
            #pragma unroll
            for (int i = 0; i < 8; ++i) {
                int flat = i * 256 + tid;
                int n = flat >> 3, c = flat & 7;
                cpa16(dst + n * SB_STRB + c * 16, src + (size_t)n * 1024 + c * 16);
            }
            CPA_COMMIT();
            CPA_WAIT1();
        } else {
            CPA_WAIT0();
        }
        __syncthreads();

        if (kb == 0) {
            #pragma unroll
            for (int am = 0; am < 4; ++am)
                #pragma unroll
                for (int an = 0; an < 8; ++an) { acc[am][an][0] = 0u; acc[am][an][1] = 0u; }
        }

        uint32_t bB = bBase + buf * B_BYTES;
        uint32_t aK = aBase + kb * 128;
        #pragma unroll
        for (int ks = 0; ks < 4; ++ks) {
            uint32_t afr[4][4], bfr[4][4];
            #pragma unroll
            for (int am = 0; am < 4; ++am) ldsm4(afr[am], aK + am * 16 * SA_STRB + ks * 32);
            #pragma unroll
            for (int t = 0; t < 4; ++t) ldsm4(bfr[t], bB + t * 16 * SB_STRB + ks * 32);
            #pragma unroll
            for (int am = 0; am < 4; ++am)
                #pragma unroll
                for (int t = 0; t < 4; ++t) {
                    mma_h(acc[am][2 * t],     afr[am], &bfr[t][0]);
                    mma_h(acc[am][2 * t + 1], afr[am], &bfr[t][2]);
                }
        }

        if (kb == 7) {
            int v0 = vc * 256;
            float2 bvv[8];
            #pragma unroll
            for (int an = 0; an < 8; ++an)
                bvv[an] = *(const float2*)&bv[v0 + wn * 64 + an * 8 + l4 * 2];
            #pragma unroll
            for (int am = 0; am < 4; ++am) {
                int rowl = wm * 64 + am * 16 + q;
                size_t gr0 = (size_t)(r0 + rowl) << 13;
                size_t gr1 = gr0 + (8u << 13);
                float mx0 = -1e30f, mx1 = -1e30f;
                float z[8][4];
                #pragma unroll
                for (int an = 0; an < 8; ++an) {
                    float2 f0 = __half22float2(*(__half2*)&acc[am][an][0]);
                    float2 f1 = __half22float2(*(__half2*)&acc[am][an][1]);
                    z[an][0] = f0.x + bvv[an].x; z[an][1] = f0.y + bvv[an].y;
                    z[an][2] = f1.x + bvv[an].x; z[an][3] = f1.y + bvv[an].y;
                    size_t coff = v0 + wn * 64 + an * 8 + l4 * 2;
                    *(float2*)&out[gr0 + coff] = make_float2(z[an][0], z[an][1]);
                    *(float2*)&out[gr1 + coff] = make_float2(z[an][2], z[an][3]);
                    mx0 = fmaxf(mx0, fmaxf(z[an][0], z[an][1]));
                    mx1 = fmaxf(mx1, fmaxf(z[an][2], z[an][3]));
                }
                mx0 = fmaxf(mx0, __shfl_xor_sync(~0u, mx0, 1));
                mx0 = fmaxf(mx0, __shfl_xor_sync(~0u, mx0, 2));
                mx1 = fmaxf(mx1, __shfl_xor_sync(~0u, mx1, 1));
                mx1 = fmaxf(mx1, __shfl_xor_sync(~0u, mx1, 2));
                float s0 = 0.f, s1 = 0.f;
                #pragma unroll
                for (int an = 0; an < 8; ++an) {
                    s0 += __expf(z[an][0] - mx0) + __expf(z[an][1] - mx0);
                    s1 += __expf(z[an][2] - mx1) + __expf(z[an][3] - mx1);
                }
                s0 += __shfl_xor_sync(~0u, s0, 1);
                s0 += __shfl_xor_sync(~0u, s0, 2);
                s1 += __shfl_xor_sync(~0u, s1, 1);
                s1 += __shfl_xor_sync(~0u, s1, 2);
                if (l4 == 0) {
                    pmax[wn][rowl] = mx0;     psum[wn][rowl] = s0;
                    pmax[wn][rowl + 8] = mx1; psum[wn][rowl + 8] = s1;
                }
            }
            __syncthreads();
            if (tid < 128) {
                float m0 = pmax[0][tid], m1 = pmax[1][tid];
                float m2 = pmax[2][tid], m3 = pmax[3][tid];
                float mo = rmax[tid];
                float mn = fmaxf(fmaxf(fmaxf(m0, m1), fmaxf(m2, m3)), mo);
                rsum[tid] = rsum[tid] * __expf(mo - mn)
                          + psum[0][tid] * __expf(m0 - mn)
                          + psum[1][tid] * __expf(m1 - mn)
                          + psum[2][tid] * __expf(m2 - mn)
                          + psum[3][tid] * __expf(m3 - mn);
                rmax[tid] = mn;
            }
        }
    }

    // ---- fused fixup: out -= lse over this CTA's 128 rows ----
    __syncthreads();
    if (tid < 128) slse[tid] = rmax[tid] + logf(rsum[tid]);
    __syncthreads();
    float4* ob = (float4*)(out + ((size_t)r0 << 13));
    #pragma unroll 4
    for (int it = 0; it < 1024; ++it) {
        int idx = it * 256 + tid;
        float l = slse[idx >> 11];
        float4 x = ob[idx];
        x.x -= l; x.y -= l; x.z -= l; x.w -= l;
        ob[idx] = x;
    }
}

// ---------------------------------------------------------------
extern "C" void kernel_launch(void* const* d_in, const int* in_sizes, int n_in,
                              void* d_out, int out_size) {
    (void)in_sizes; (void)n_in; (void)out_size;
    const float* v  = (const float*)d_in[0];
    const float* t  = (const float*)d_in[1];
    const float* W1 = (const float*)d_in[2];
    const float* b1 = (const float*)d_in[3];
    const float* W2 = (const float*)d_in[4];
    const float* b2 = (const float*)d_in[5];
    const float* Wv = (const float*)d_in[6];
    const float* bvp = (const float*)d_in[7];
    float* out = (float*)d_out;

    k_encdec<<<160, 256>>>(v, t, W1, b1, W2, b2);
    k_cvt<<<4096, 256>>>(Wv);
    cudaFuncSetAttribute(k_gemm2, cudaFuncAttributeMaxDynamicSharedMemorySize, DYN_SMEM);
    k_gemm2<<<256, 256, DYN_SMEM>>>(bvp, out);
}

// round 6
// speedup vs baseline: 1.0011x; 1.0011x over previous
#include <cuda_runtime.h>
#include <cuda_bf16.h>
#include <cuda_fp16.h>
#include <math.h>
#include <stdint.h>

#define VSZ 8192

__device__ __align__(16) float g_enc[512 * 512];
__device__ __align__(16) float g_dec[128 * 512];
__device__ __align__(16) __half g_wvt[8192 * 512];   // [v][d] fp16

// ---------------- helpers ----------------
__device__ __forceinline__ uint32_t smem_u32(const void* p) {
    uint32_t a;
    asm("{ .reg .u64 t; cvta.to.shared.u64 t, %1; cvt.u32.u64 %0, t; }" : "=r"(a) : "l"(p));
    return a;
}
__device__ __forceinline__ void cpa16(uint32_t dst, const void* src) {
    asm volatile("cp.async.cg.shared.global [%0], [%1], 16;" :: "r"(dst), "l"(src));
}
#define CPA_COMMIT() asm volatile("cp.async.commit_group;" ::: "memory")
#define CPA_WAIT1()  asm volatile("cp.async.wait_group 1;" ::: "memory")
#define CPA_WAIT0()  asm volatile("cp.async.wait_group 0;" ::: "memory")

__device__ __forceinline__ void ldsm4(uint32_t* r, uint32_t a) {
    asm volatile("ldmatrix.sync.aligned.m8n8.x4.shared.b16 {%0,%1,%2,%3}, [%4];"
        : "=r"(r[0]), "=r"(r[1]), "=r"(r[2]), "=r"(r[3]) : "r"(a));
}
// fp16 inputs, fp16 accumulators (2 packed b32 regs)
__device__ __forceinline__ void mma_h(uint32_t* c, const uint32_t* a, const uint32_t* b) {
    asm("mma.sync.aligned.m16n8k16.row.col.f16.f16.f16.f16 "
        "{%0,%1}, {%2,%3,%4,%5}, {%6,%7}, {%0,%1};\n"
        : "+r"(c[0]), "+r"(c[1])
        : "r"(a[0]), "r"(a[1]), "r"(a[2]), "r"(a[3]), "r"(b[0]), "r"(b[1]));
}

// ---------------- prep kernels ----------------
// 4 rows per CTA: enc groups (bid<128), dec groups (bid>=128)
__global__ void k_encdec(const float* __restrict__ v, const float* __restrict__ t,
                         const float* __restrict__ W1, const float* __restrict__ b1,
                         const float* __restrict__ W2, const float* __restrict__ b2) {
    __shared__ float xr[4][512];
    int bid = blockIdx.x, tid = threadIdx.x;
    const float *in, *W, *bs; float* out;
    if (bid < 128) { in = v + (size_t)bid * 2048; W = W1; bs = b1; out = g_enc + (size_t)bid * 2048; }
    else { int r = bid - 128; in = t + (size_t)r * 2048; W = W2; bs = b2; out = g_dec + (size_t)r * 2048; }
    #pragma unroll
    for (int i = 0; i < 8; ++i) ((float*)xr)[i * 256 + tid] = in[i * 256 + tid];
    __syncthreads();
    int e = tid * 2;
    float b0 = bs[e], b1v = bs[e + 1];
    float a00 = b0, a01 = b1v, a10 = b0, a11 = b1v;
    float a20 = b0, a21 = b1v, a30 = b0, a31 = b1v;
    #pragma unroll 4
    for (int d = 0; d < 512; ++d) {
        float2 w = *(const float2*)&W[d * 512 + e];
        float x0 = xr[0][d], x1 = xr[1][d], x2 = xr[2][d], x3 = xr[3][d];
        a00 = fmaf(x0, w.x, a00); a01 = fmaf(x0, w.y, a01);
        a10 = fmaf(x1, w.x, a10); a11 = fmaf(x1, w.y, a11);
        a20 = fmaf(x2, w.x, a20); a21 = fmaf(x2, w.y, a21);
        a30 = fmaf(x3, w.x, a30); a31 = fmaf(x3, w.y, a31);
    }
    out[e] = a00;        out[e + 1] = a01;
    out[512 + e] = a10;  out[512 + e + 1] = a11;
    out[1024 + e] = a20; out[1024 + e + 1] = a21;
    out[1536 + e] = a30; out[1536 + e + 1] = a31;
}

__global__ void k_cvt(const float* __restrict__ Wv) {
    __shared__ float tile[32][33];
    int bvi = blockIdx.x & 255, bd = blockIdx.x >> 8;
    int v0 = bvi * 32, d0 = bd * 32;
    int c = threadIdx.x & 31, r8 = threadIdx.x >> 5;
    #pragma unroll
    for (int i = 0; i < 4; ++i) {
        int d = i * 8 + r8;
        tile[d][c] = Wv[(size_t)(d0 + d) * VSZ + v0 + c];
    }
    __syncthreads();
    #pragma unroll
    for (int i = 0; i < 4; ++i) {
        int vv = i * 8 + r8;
        g_wvt[(size_t)(v0 + vv) * 512 + d0 + c] = __float2half(tile[c][vv]);
    }
}

// ---------------- main GEMM + fused log-softmax ----------------
// CTA: 128 rows x full V. 8 warps, 2(M) x 4(N), warp tile 64x64, fp16 acc.
#define SA_STRB 1040                 // A row stride bytes (520 fp16)
#define SB_STRB 144                  // B row stride bytes (72 fp16)
#define A_BYTES (128 * SA_STRB)
#define B_BYTES (256 * SB_STRB)
#define DYN_SMEM (A_BYTES + 2 * B_BYTES)

__global__ void __launch_bounds__(256, 1)
k_gemm2(const float* __restrict__ bv, float* __restrict__ out) {
    extern __shared__ char sm[];
    __shared__ float pmax[4][128], psum[4][128];
    __shared__ float rmax[128], rsum[128], slse[128];

    const uint32_t sA = smem_u32(sm);
    const uint32_t sB0 = sA + A_BYTES;
    int tid = threadIdx.x, lane = tid & 31, w = tid >> 5;
    int wm = w >> 2, wn = w & 3;
    int q = lane >> 2, l4 = lane & 3;
    int r0 = blockIdx.x * 128;

    // ---- build A tile (relu(enc+dec) -> fp16) ----
    #pragma unroll 1
    for (int i = 0; i < 32; ++i) {
        int idx = i * 256 + tid;
        int r = idx >> 6, g = idx & 63;
        int grow = r0 + r;
        int er = grow >> 6;
        int dr = ((grow >> 14) << 6) | (grow & 63);
        const float* ep = g_enc + (size_t)er * 512 + g * 8;
        const float* dp = g_dec + (size_t)dr * 512 + g * 8;
        float4 e0 = *(const float4*)ep, e1 = *(const float4*)(ep + 4);
        float4 d0 = *(const float4*)dp, d1 = *(const float4*)(dp + 4);
        __half2 p0 = __floats2half2_rn(fmaxf(e0.x + d0.x, 0.f), fmaxf(e0.y + d0.y, 0.f));
        __half2 p1 = __floats2half2_rn(fmaxf(e0.z + d0.z, 0.f), fmaxf(e0.w + d0.w, 0.f));
        __half2 p2 = __floats2half2_rn(fmaxf(e1.x + d1.x, 0.f), fmaxf(e1.y + d1.y, 0.f));
        __half2 p3 = __floats2half2_rn(fmaxf(e1.z + d1.z, 0.f), fmaxf(e1.w + d1.w, 0.f));
        uint4 u;
        u.x = *(unsigned*)&p0; u.y = *(unsigned*)&p1; u.z = *(unsigned*)&p2; u.w = *(unsigned*)&p3;
        *(uint4*)(sm + r * SA_STRB + g * 16) = u;
    }
    if (tid < 128) { rmax[tid] = -1e30f; rsum[tid] = 0.f; }

    const uint32_t aBase = sA + (wm * 64 + (lane & 15)) * SA_STRB + (lane >> 4) * 16;
    const int bN = (lane & 7) + ((lane >> 4) << 3);
    const uint32_t bKh = ((lane >> 3) & 1) * 16;
    const uint32_t bBase = sB0 + (wn * 64 + bN) * SB_STRB + bKh;

    uint32_t acc[4][8][2];   // fp16x2 accumulators

    // stage slab 0
    {
        #pragma unroll
        for (int i = 0; i < 8; ++i) {
            int flat = i * 256 + tid;
            int n = flat >> 3, c = flat & 7;
            cpa16(sB0 + n * SB_STRB + c * 16, (const char*)g_wvt + (size_t)n * 1024 + c * 16);
        }
        CPA_COMMIT();
    }

    #pragma unroll 1
    for (int s = 0; s < 256; ++s) {
        int vc = s >> 3, kb = s & 7, buf = s & 1;
        __syncthreads();
        if (s + 1 < 256) {
            int vn = (s + 1) >> 3, kn = (s + 1) & 7;
            uint32_t dst = sB0 + ((s + 1) & 1) * B_BYTES;
            const char* src = (const char*)g_wvt + (size_t)vn * 256 * 1024 + kn * 128;
            #pragma unroll
            for (int i = 0; i < 8; ++i) {
                int flat = i * 256 + tid;
                int n = flat >> 3, c = flat & 7;
                cpa16(dst + n * SB_STRB + c * 16, src + (size_t)n * 1024 + c * 16);
            }
            CPA_COMMIT();
            CPA_WAIT1();
        } else {
            CPA_WAIT0();
        }
        __syncthreads();

        if (kb == 0) {
            #pragma unroll
            for (int am = 0; am < 4; ++am)
                #pragma unroll
                for (int an = 0; an < 8; ++an) { acc[am][an][0] = 0u; acc[am][an][1] = 0u; }
        }

        uint32_t bB = bBase + buf * B_BYTES;
        uint32_t aK = aBase + kb * 128;
        #pragma unroll
        for (int ks = 0; ks < 4; ++ks) {
            uint32_t afr[4][4], bfr[4][4];
            #pragma unroll
            for (int am = 0; am < 4; ++am) ldsm4(afr[am], aK + am * 16 * SA_STRB + ks * 32);
            #pragma unroll
            for (int t = 0; t < 4; ++t) ldsm4(bfr[t], bB + t * 16 * SB_STRB + ks * 32);
            #pragma unroll
            for (int am = 0; am < 4; ++am)
                #pragma unroll
                for (int t = 0; t < 4; ++t) {
                    mma_h(acc[am][2 * t],     afr[am], &bfr[t][0]);
                    mma_h(acc[am][2 * t + 1], afr[am], &bfr[t][2]);
                }
        }

        if (kb == 7) {
            int v0 = vc * 256;
            float2 bvv[8];
            #pragma unroll
            for (int an = 0; an < 8; ++an)
                bvv[an] = *(const float2*)&bv[v0 + wn * 64 + an * 8 + l4 * 2];
            #pragma unroll
            for (int am = 0; am < 4; ++am) {
                int rowl = wm * 64 + am * 16 + q;
                size_t gr0 = (size_t)(r0 + rowl) << 13;
                size_t gr1 = gr0 + (8u << 13);
                float mx0 = -1e30f, mx1 = -1e30f;
                float z[8][4];
                #pragma unroll
                for (int an = 0; an < 8; ++an) {
                    float2 f0 = __half22float2(*(__half2*)&acc[am][an][0]);
                    float2 f1 = __half22float2(*(__half2*)&acc[am][an][1]);
                    z[an][0] = f0.x + bvv[an].x; z[an][1] = f0.y + bvv[an].y;
                    z[an][2] = f1.x + bvv[an].x; z[an][3] = f1.y + bvv[an].y;
                    size_t coff = v0 + wn * 64 + an * 8 + l4 * 2;
                    *(float2*)&out[gr0 + coff] = make_float2(z[an][0], z[an][1]);
                    *(float2*)&out[gr1 + coff] = make_float2(z[an][2], z[an][3]);
                    mx0 = fmaxf(mx0, fmaxf(z[an][0], z[an][1]));
                    mx1 = fmaxf(mx1, fmaxf(z[an][2], z[an][3]));
                }
                mx0 = fmaxf(mx0, __shfl_xor_sync(~0u, mx0, 1));
                mx0 = fmaxf(mx0, __shfl_xor_sync(~0u, mx0, 2));
                mx1 = fmaxf(mx1, __shfl_xor_sync(~0u, mx1, 1));
                mx1 = fmaxf(mx1, __shfl_xor_sync(~0u, mx1, 2));
                float s0 = 0.f, s1 = 0.f;
                #pragma unroll
                for (int an = 0; an < 8; ++an) {
                    s0 += __expf(z[an][0] - mx0) + __expf(z[an][1] - mx0);
                    s1 += __expf(z[an][2] - mx1) + __expf(z[an][3] - mx1);
                }
                s0 += __shfl_xor_sync(~0u, s0, 1);
                s0 += __shfl_xor_sync(~0u, s0, 2);
                s1 += __shfl_xor_sync(~0u, s1, 1);
                s1 += __shfl_xor_sync(~0u, s1, 2);
                if (l4 == 0) {
                    pmax[wn][rowl] = mx0;     psum[wn][rowl] = s0;
                    pmax[wn][rowl + 8] = mx1; psum[wn][rowl + 8] = s1;
                }
            }
            __syncthreads();
            if (tid < 128) {
                float m0 = pmax[0][tid], m1 = pmax[1][tid];
                float m2 = pmax[2][tid], m3 = pmax[3][tid];
                float mo = rmax[tid];
                float mn = fmaxf(fmaxf(fmaxf(m0, m1), fmaxf(m2, m3)), mo);
                rsum[tid] = rsum[tid] * __expf(mo - mn)
                          + psum[0][tid] * __expf(m0 - mn)
                          + psum[1][tid] * __expf(m1 - mn)
                          + psum[2][tid] * __expf(m2 - mn)
                          + psum[3][tid] * __expf(m3 - mn);
                rmax[tid] = mn;
            }
        }
    }

    // ---- fused fixup: out -= lse over this CTA's 128 rows ----
    __syncthreads();
    if (tid < 128) slse[tid] = rmax[tid] + logf(rsum[tid]);
    __syncthreads();
    float4* ob = (float4*)(out + ((size_t)r0 << 13));
    #pragma unroll 4
    for (int it = 0; it < 1024; ++it) {
        int idx = it * 256 + tid;
        float l = slse[idx >> 11];
        float4 x = ob[idx];
        x.x -= l; x.y -= l; x.z -= l; x.w -= l;
        ob[idx] = x;
    }
}

// ---------------------------------------------------------------
extern "C" void kernel_launch(void* const* d_in, const int* in_sizes, int n_in,
                              void* d_out, int out_size) {
    (void)in_sizes; (void)n_in; (void)out_size;
    const float* v  = (const float*)d_in[0];
    const float* t  = (const float*)d_in[1];
    const float* W1 = (const float*)d_in[2];
    const float* b1 = (const float*)d_in[3];
    const float* W2 = (const float*)d_in[4];
    const float* b2 = (const float*)d_in[5];
    const float* Wv = (const float*)d_in[6];
    const float* bvp = (const float*)d_in[7];
    float* out = (float*)d_out;

    k_encdec<<<160, 256>>>(v, t, W1, b1, W2, b2);
    k_cvt<<<4096, 256>>>(Wv);
    cudaFuncSetAttribute(k_gemm2, cudaFuncAttributeMaxDynamicSharedMemorySize, DYN_SMEM);
    k_gemm2<<<256, 256, DYN_SMEM>>>(bvp, out);
}